// round 14
// baseline (speedup 1.0000x reference)
#include <cuda_runtime.h>
#include <cuda_fp16.h>

// GCNRFPEncode — CSR gather-side aggregation, no float atomics.
// out = BN( 0.5*invsq[s]*sum_{dst in adj[s]} g[dst] + 0.5*deg[s]^1.5*g[s] )
// g[v] = rsqrt(deg[v]) * (X[v]@W + b)
// Graph-prep branch (offal+scatter) overlapped with the GEMM via a side stream.
// Gather: 8 lanes/node, uint4 fp16 loads, 4 independent chains per warp.

#define FF 128
#define HH 64
#define NMAX 100000
#define EMAX 2000000
#define BN_EPS 0.001f

__device__ int    g_degi[NMAX];
__device__ int    g_off[NMAX];
__device__ int    g_cursor[NMAX];
__device__ int    g_adj[EMAX];
__device__ int    g_total;
__device__ float  g_g[(size_t)NMAX * HH];
__device__ __half g_g16[(size_t)NMAX * HH];

// ---------------- packed f32x2 helpers ------------------------------------------
__device__ __forceinline__ unsigned long long ffma2(unsigned long long a,
                                                    unsigned long long b,
                                                    unsigned long long c) {
    unsigned long long d;
    asm("fma.rn.f32x2 %0, %1, %2, %3;" : "=l"(d) : "l"(a), "l"(b), "l"(c));
    return d;
}
__device__ __forceinline__ float2 unpack2(unsigned long long v) {
    float2 r;
    asm("mov.b64 {%0, %1}, %2;" : "=f"(r.x), "=f"(r.y) : "l"(v));
    return r;
}

// ---------------- zero degree counters + ticket ----------------------------------
__global__ void k_zero(int N) {
    int t = blockIdx.x * blockDim.x + threadIdx.x;
    if (t < N) g_degi[t] = 0;
    if (t == 0) g_total = 0;
}

// ---------------- degree count (int RED) ------------------------------------------
__global__ void k_deg(const int2* __restrict__ edge, int E) {
    int t = blockIdx.x * blockDim.x + threadIdx.x;
    if (t < E) atomicAdd(&g_degi[edge[t].x], 1);
}

// ---------------- offset allocation: warp scan + one atomic per warp --------------
__global__ __launch_bounds__(256) void k_offal(int N) {
    int t = blockIdx.x * 256 + threadIdx.x;
    int lane = threadIdx.x & 31;
    int d = (t < N) ? g_degi[t] : 0;
    int v = d;
#pragma unroll
    for (int o = 1; o < 32; o <<= 1) {
        int u = __shfl_up_sync(0xffffffffu, v, o);
        if (lane >= o) v += u;
    }
    int wbase = 0;
    if (lane == 31) wbase = atomicAdd(&g_total, v);
    wbase = __shfl_sync(0xffffffffu, wbase, 31);
    int excl = wbase + v - d;
    if (t < N) {
        g_off[t] = excl;
        g_cursor[t] = excl;
    }
}

// ---------------- scatter edges into CSR buckets (2 edges/thread) ------------------
__global__ void k_scatter(const int4* __restrict__ edge2, int E) {
    int t = blockIdx.x * blockDim.x + threadIdx.x;
    int e0 = t * 2;
    if (e0 + 1 < E) {
        int4 sd = edge2[t];                      // (src0,dst0,src1,dst1)
        int p0 = atomicAdd(&g_cursor[sd.x], 1);
        int p1 = atomicAdd(&g_cursor[sd.z], 1);
        g_adj[p0] = sd.y;
        g_adj[p1] = sd.w;
    } else if (e0 < E) {
        const int2* e = (const int2*)edge2;
        int2 sd = e[e0];
        int p = atomicAdd(&g_cursor[sd.x], 1);
        g_adj[p] = sd.y;
    }
}

// ---------------- GEMM: g = (X@W + b) * rsqrt(deg), fp32 + fp16 copies -------------
extern __shared__ unsigned long long g_smem[];

__global__ __launch_bounds__(256, 2) void k_gemm(const float* __restrict__ X,
                                                 const float* __restrict__ W,
                                                 const float* __restrict__ b,
                                                 int N) {
    ulonglong2* sX = (ulonglong2*)g_smem;            // 128 rows x 32 k4 = 64 KB
    ulonglong2* sW = sX + 128 * 32;                  // 32 k4 x 64 col  = 32 KB
    float4* sX4 = (float4*)sX;
    float4* sW4 = (float4*)sW;

    int tid = threadIdx.x;
    int row0 = blockIdx.x * 128;
    int maxr = N - row0;

    const float4* Xg = (const float4*)X + (size_t)row0 * 32;
#pragma unroll
    for (int it = 0; it < 16; it++) {
        int i = tid + it * 256;
        int r = i >> 5;
        float4 v = make_float4(0.f, 0.f, 0.f, 0.f);
        if (r < maxr) v = Xg[i];
        sX4[i] = v;
    }
#pragma unroll
    for (int it = 0; it < 8; it++) {
        int j = tid + it * 256;
        int col = j & 63, k4 = j >> 6;
        float4 w;
        w.x = W[(4 * k4 + 0) * HH + col];
        w.y = W[(4 * k4 + 1) * HH + col];
        w.z = W[(4 * k4 + 2) * HH + col];
        w.w = W[(4 * k4 + 3) * HH + col];
        sW4[j] = w;
    }
    __syncthreads();

    int tx = tid & 15;
    int ty = tid >> 4;
    int r0 = ty * 8;

    float bv[4];
#pragma unroll
    for (int c = 0; c < 4; c++) bv[c] = b[tx + 16 * c];

    unsigned long long acc[8][4];
#pragma unroll
    for (int r = 0; r < 8; r++)
#pragma unroll
        for (int c = 0; c < 4; c++) acc[r][c] = 0ull;

#pragma unroll 2
    for (int k4 = 0; k4 < 32; k4++) {
        ulonglong2 w0 = sW[k4 * 64 + tx];
        ulonglong2 w1 = sW[k4 * 64 + tx + 16];
        ulonglong2 w2 = sW[k4 * 64 + tx + 32];
        ulonglong2 w3 = sW[k4 * 64 + tx + 48];
#pragma unroll
        for (int r = 0; r < 8; r++) {
            ulonglong2 x = sX[(r0 + r) * 32 + k4];
            acc[r][0] = ffma2(x.x, w0.x, acc[r][0]);
            acc[r][1] = ffma2(x.x, w1.x, acc[r][1]);
            acc[r][2] = ffma2(x.x, w2.x, acc[r][2]);
            acc[r][3] = ffma2(x.x, w3.x, acc[r][3]);
            acc[r][0] = ffma2(x.y, w0.y, acc[r][0]);
            acc[r][1] = ffma2(x.y, w1.y, acc[r][1]);
            acc[r][2] = ffma2(x.y, w2.y, acc[r][2]);
            acc[r][3] = ffma2(x.y, w3.y, acc[r][3]);
        }
    }

#pragma unroll
    for (int r = 0; r < 8; r++) {
        int row = row0 + r0 + r;
        if (row < N) {
            float is = rsqrtf((float)g_degi[row]);
            float*  gp = g_g   + (size_t)row * HH;
            __half* hp = g_g16 + (size_t)row * HH;
#pragma unroll
            for (int c = 0; c < 4; c++) {
                float2 p = unpack2(acc[r][c]);
                float val = (p.x + p.y + bv[c]) * is;
                gp[tx + 16 * c] = val;
                hp[tx + 16 * c] = __float2half_rn(val);
            }
        }
    }
}

// ---------------- gather + finalize (fused): 8 lanes/node, MLP=8 --------------------
// Lane q of a node-group owns fp16 features [8q, 8q+8) = one uint4 (16 B).
// A row gather = 8 lanes x 16B = one 128B wavefront; 4 independent chains per warp.
__global__ void k_gather(float* __restrict__ out,
                         const float* __restrict__ gamma,
                         const float* __restrict__ beta,
                         const float* __restrict__ mean,
                         const float* __restrict__ var,
                         int N) {
    int t = blockIdx.x * blockDim.x + threadIdx.x;
    int v = t >> 3, q = t & 7;
    if (v >= N) return;

    int beg = g_off[v];
    int dgi = g_degi[v];
    int end = beg + dgi;

    float acc[8] = {0.f, 0.f, 0.f, 0.f, 0.f, 0.f, 0.f, 0.f};

    int i = beg;
    for (; i + 8 <= end; i += 8) {
        int idx[8];
#pragma unroll
        for (int e = 0; e < 8; e++) idx[e] = __ldg(&g_adj[i + e]);
        uint4 u[8];
#pragma unroll
        for (int e = 0; e < 8; e++)
            u[e] = __ldg((const uint4*)(g_g16 + (size_t)idx[e] * HH) + q);
#pragma unroll
        for (int e = 0; e < 8; e++) {
            float2 a0 = __half22float2(*(const __half2*)&u[e].x);
            float2 a1 = __half22float2(*(const __half2*)&u[e].y);
            float2 a2 = __half22float2(*(const __half2*)&u[e].z);
            float2 a3 = __half22float2(*(const __half2*)&u[e].w);
            acc[0] += a0.x; acc[1] += a0.y; acc[2] += a1.x; acc[3] += a1.y;
            acc[4] += a2.x; acc[5] += a2.y; acc[6] += a3.x; acc[7] += a3.y;
        }
    }
    for (; i < end; i++) {
        int d = __ldg(&g_adj[i]);
        uint4 u = __ldg((const uint4*)(g_g16 + (size_t)d * HH) + q);
        float2 a0 = __half22float2(*(const __half2*)&u.x);
        float2 a1 = __half22float2(*(const __half2*)&u.y);
        float2 a2 = __half22float2(*(const __half2*)&u.z);
        float2 a3 = __half22float2(*(const __half2*)&u.w);
        acc[0] += a0.x; acc[1] += a0.y; acc[2] += a1.x; acc[3] += a1.y;
        acc[4] += a2.x; acc[5] += a2.y; acc[6] += a3.x; acc[7] += a3.y;
    }

    float dg = (float)dgi;
    float hs = 0.5f * rsqrtf(dg);          // 0.5 * deg^-1/2
    float sc = 0.5f * dg * sqrtf(dg);      // 0.5 * deg^1.5

    const float* gp = g_g + (size_t)v * HH + q * 8;
    float4 gs0 = __ldg((const float4*)gp);
    float4 gs1 = __ldg((const float4*)gp + 1);
    float gv[8] = {gs0.x, gs0.y, gs0.z, gs0.w, gs1.x, gs1.y, gs1.z, gs1.w};

    int j = q * 8;
    float o[8];
#pragma unroll
    for (int c = 0; c < 8; c++) {
        float a = hs * acc[c] + sc * gv[c];
        float scale = gamma[j + c] * rsqrtf(var[j + c] + BN_EPS);
        o[c] = (a - mean[j + c]) * scale + beta[j + c];
    }
    float* op = out + (size_t)v * HH + j;
    *(float4*)op       = make_float4(o[0], o[1], o[2], o[3]);
    *((float4*)op + 1) = make_float4(o[4], o[5], o[6], o[7]);
}

// ---------------- launch --------------------------------------------------------------
extern "C" void kernel_launch(void* const* d_in, const int* in_sizes, int n_in,
                              void* d_out, int out_size) {
    const float* X     = (const float*)d_in[0];
    const float* W     = (const float*)d_in[1];
    const float* b     = (const float*)d_in[2];
    const float* gamma = (const float*)d_in[3];
    const float* beta  = (const float*)d_in[4];
    const float* mean  = (const float*)d_in[5];
    const float* var   = (const float*)d_in[6];
    const int2*  edge  = (const int2*)d_in[7];

    int N = in_sizes[0] / FF;
    int E = in_sizes[7] / 2;
    float* out = (float*)d_out;

    static cudaStream_t s2 = nullptr;
    static cudaEvent_t evA = nullptr, evB = nullptr;
    static bool inited = false;
    if (!inited) {
        cudaStreamCreateWithFlags(&s2, cudaStreamNonBlocking);
        cudaEventCreateWithFlags(&evA, cudaEventDisableTiming);
        cudaEventCreateWithFlags(&evB, cudaEventDisableTiming);
        cudaFuncSetAttribute(k_gemm, cudaFuncAttributeMaxDynamicSharedMemorySize, 96 * 1024);
        inited = true;
    }

    // main stream: zero -> deg -> (fork) -> gemm -> (join) -> gather
    k_zero<<<(N + 255) / 256, 256>>>(N);
    k_deg<<<(E + 255) / 256, 256>>>(edge, E);
    cudaEventRecord(evA, 0);

    // side stream: offal -> scatter (independent of gemm)
    cudaStreamWaitEvent(s2, evA, 0);
    k_offal<<<(N + 255) / 256, 256, 0, s2>>>(N);
    {
        int nt = (E + 1) / 2;
        k_scatter<<<(nt + 255) / 256, 256, 0, s2>>>((const int4*)edge, E);
    }
    cudaEventRecord(evB, s2);

    k_gemm<<<(N + 127) / 128, 256, 96 * 1024>>>(X, W, b, N);
    cudaStreamWaitEvent(0, evB, 0);
    k_gather<<<(N * 8 + 255) / 256, 256>>>(out, gamma, beta, mean, var, N);
}

// round 15
// speedup vs baseline: 1.2750x; 1.2750x over previous
#include <cuda_runtime.h>
#include <cuda_fp16.h>
#include <cuda_bf16.h>
#include <cstdint>

// GCNRFPEncode — CSR gather-side aggregation + split-bf16 HMMA GEMM.
// out = BN( 0.5*invsq[s]*sum_{dst in adj[s]} g[dst] + 0.5*deg[s]^1.5*g[s] )
// g[v] = rsqrt(deg[v]) * (X[v]@W + b)

#define FF 128
#define HH 64
#define NMAX 100000
#define EMAX 2000000
#define BN_EPS 0.001f

__device__ int    g_degi[NMAX];
__device__ int    g_off[NMAX];
__device__ int    g_cursor[NMAX];
__device__ int    g_adj[EMAX];
__device__ int    g_total;
__device__ float  g_g[(size_t)NMAX * HH];
__device__ __half g_g16[(size_t)NMAX * HH];

// ---------------- zero degree counters + ticket ----------------------------------
__global__ void k_zero(int N) {
    int t = blockIdx.x * blockDim.x + threadIdx.x;
    if (t < N) g_degi[t] = 0;
    if (t == 0) g_total = 0;
}

// ---------------- degree count (int RED) ------------------------------------------
__global__ void k_deg(const int2* __restrict__ edge, int E) {
    int t = blockIdx.x * blockDim.x + threadIdx.x;
    if (t < E) atomicAdd(&g_degi[edge[t].x], 1);
}

// ---------------- offset allocation: warp scan + one atomic per warp --------------
__global__ __launch_bounds__(256) void k_offal(int N) {
    int t = blockIdx.x * 256 + threadIdx.x;
    int lane = threadIdx.x & 31;
    int d = (t < N) ? g_degi[t] : 0;
    int v = d;
#pragma unroll
    for (int o = 1; o < 32; o <<= 1) {
        int u = __shfl_up_sync(0xffffffffu, v, o);
        if (lane >= o) v += u;
    }
    int wbase = 0;
    if (lane == 31) wbase = atomicAdd(&g_total, v);
    wbase = __shfl_sync(0xffffffffu, wbase, 31);
    int excl = wbase + v - d;
    if (t < N) {
        g_off[t] = excl;
        g_cursor[t] = excl;
    }
}

// ---------------- scatter edges into CSR buckets (2 edges/thread) ------------------
__global__ void k_scatter(const int4* __restrict__ edge2, int E) {
    int t = blockIdx.x * blockDim.x + threadIdx.x;
    int e0 = t * 2;
    if (e0 + 1 < E) {
        int4 sd = edge2[t];
        int p0 = atomicAdd(&g_cursor[sd.x], 1);
        int p1 = atomicAdd(&g_cursor[sd.z], 1);
        g_adj[p0] = sd.y;
        g_adj[p1] = sd.w;
    } else if (e0 < E) {
        const int2* e = (const int2*)edge2;
        int2 sd = e[e0];
        int p = atomicAdd(&g_cursor[sd.x], 1);
        g_adj[p] = sd.y;
    }
}

// ---------------- HMMA GEMM: g = (X@W + b) * rsqrt(deg) ----------------------------
// CTA: 128 rows x 64 cols, K=128. 8 warps, each m16 x n64.
// X, W split to bf16 hi/lo; D = Ah*Bh + Ah*Bl + Al*Bh (fp32 accum).
// smem: sAh/sAl 128x256B (row-major, 16B-XOR swizzle), sBh/sBl 128x128B ([k][n]).

#define SA_H 0
#define SA_L 32768
#define SB_H 65536
#define SB_L 81920
#define SM_TOT 98304

__device__ __forceinline__ uint32_t bf2(float hi, float lo) {
    __nv_bfloat162 v = __floats2bfloat162_rn(hi, lo);
    return *(uint32_t*)&v;
}

extern __shared__ char gsm[];

__global__ __launch_bounds__(256, 2) void k_gemm(const float* __restrict__ X,
                                                 const float* __restrict__ W,
                                                 const float* __restrict__ b,
                                                 int N) {
    uint32_t sbase;
    asm("{ .reg .u64 t; cvta.to.shared.u64 t, %1; cvt.u32.u64 %0, t; }"
        : "=r"(sbase) : "l"(gsm));

    int tid = threadIdx.x;
    int lane = tid & 31;
    int wid = tid >> 5;
    int row0 = blockIdx.x * 128;
    int maxr = N - row0;

    // ---- stage A: X[row0..row0+128) x 128k, fp32 -> bf16 hi/lo, swizzled ----
    const float4* Xg = (const float4*)(X + (size_t)row0 * FF);
#pragma unroll
    for (int it = 0; it < 16; it++) {
        int i = tid + it * 256;             // 4096 float4
        int r = i >> 5, c4 = i & 31;        // k = c4*4
        float4 v = make_float4(0.f, 0.f, 0.f, 0.f);
        if (r < maxr) v = Xg[i];
        float h0 = __bfloat162float(__float2bfloat16_rn(v.x));
        float h1 = __bfloat162float(__float2bfloat16_rn(v.y));
        float h2 = __bfloat162float(__float2bfloat16_rn(v.z));
        float h3 = __bfloat162float(__float2bfloat16_rn(v.w));
        uint2 hi = make_uint2(bf2(h0, h1), bf2(h2, h3));
        uint2 lo = make_uint2(bf2(v.x - h0, v.y - h1), bf2(v.z - h2, v.w - h3));
        uint32_t off = r * 256 + (((c4 >> 1) ^ (r & 7)) << 4) + ((c4 & 1) << 3);
        *(uint2*)(gsm + SA_H + off) = hi;
        *(uint2*)(gsm + SA_L + off) = lo;
    }
    // ---- stage B: W[k][n] fp32 -> bf16 hi/lo, [k rows][64 n], swizzled ----
#pragma unroll
    for (int it = 0; it < 8; it++) {
        int i = tid + it * 256;             // 2048 float4
        int k = i >> 4, q = i & 15;         // n = q*4
        float4 v = ((const float4*)W)[i];
        float h0 = __bfloat162float(__float2bfloat16_rn(v.x));
        float h1 = __bfloat162float(__float2bfloat16_rn(v.y));
        float h2 = __bfloat162float(__float2bfloat16_rn(v.z));
        float h3 = __bfloat162float(__float2bfloat16_rn(v.w));
        uint2 hi = make_uint2(bf2(h0, h1), bf2(h2, h3));
        uint2 lo = make_uint2(bf2(v.x - h0, v.y - h1), bf2(v.z - h2, v.w - h3));
        uint32_t off = k * 128 + (((q >> 1) ^ (k & 7)) << 4) + ((q & 1) << 3);
        *(uint2*)(gsm + SB_H + off) = hi;
        *(uint2*)(gsm + SB_L + off) = lo;
    }
    __syncthreads();

    // ---- mma mainloop: warp wid owns rows [wid*16, wid*16+16) ----
    float acc[8][4];
#pragma unroll
    for (int j = 0; j < 8; j++)
#pragma unroll
        for (int c = 0; c < 4; c++) acc[j][c] = 0.f;

    // A ldmatrix lane address precompute: matrix m = lane>>3
    int am = lane >> 3;
    int arow = wid * 16 + ((am & 1) << 3) + (lane & 7);
    uint32_t a_rowoff = arow * 256;
    int a_rx = arow & 7;
    int a_mh = am >> 1;

    // B ldmatrix lane address: rows k0 + ((lane>>3)&1)*8 + (lane&7), n-chunk (lane>>4)
    int brow_in = (((lane >> 3) & 1) << 3) + (lane & 7);
    int b_nc_half = lane >> 4;               // 0 or 1 -> n offset 0/8 within 16-chunk

#pragma unroll
    for (int s = 0; s < 8; s++) {
        uint32_t ah[4], al[4];
        {
            uint32_t cell = (uint32_t)((2 * s + a_mh) ^ a_rx) << 4;
            uint32_t aaddr_h = sbase + SA_H + a_rowoff + cell;
            uint32_t aaddr_l = aaddr_h + (SA_L - SA_H);
            asm volatile("ldmatrix.sync.aligned.m8n8.x4.shared.b16 {%0,%1,%2,%3}, [%4];"
                         : "=r"(ah[0]), "=r"(ah[1]), "=r"(ah[2]), "=r"(ah[3]) : "r"(aaddr_h));
            asm volatile("ldmatrix.sync.aligned.m8n8.x4.shared.b16 {%0,%1,%2,%3}, [%4];"
                         : "=r"(al[0]), "=r"(al[1]), "=r"(al[2]), "=r"(al[3]) : "r"(aaddr_l));
        }
        int kk = s * 16 + brow_in;
        uint32_t b_rowoff = kk * 128;
        int b_kx = kk & 7;
#pragma unroll
        for (int nc = 0; nc < 4; nc++) {
            uint32_t bh[4], bl[4];
            uint32_t cell = (uint32_t)((2 * nc + b_nc_half) ^ b_kx) << 4;
            uint32_t baddr_h = sbase + SB_H + b_rowoff + cell;
            uint32_t baddr_l = baddr_h + (SB_L - SB_H);
            asm volatile("ldmatrix.sync.aligned.m8n8.x4.trans.shared.b16 {%0,%1,%2,%3}, [%4];"
                         : "=r"(bh[0]), "=r"(bh[1]), "=r"(bh[2]), "=r"(bh[3]) : "r"(baddr_h));
            asm volatile("ldmatrix.sync.aligned.m8n8.x4.trans.shared.b16 {%0,%1,%2,%3}, [%4];"
                         : "=r"(bl[0]), "=r"(bl[1]), "=r"(bl[2]), "=r"(bl[3]) : "r"(baddr_l));
#pragma unroll
            for (int a2 = 0; a2 < 2; a2++) {
                int j = nc * 2 + a2;
#define MMA(A, B0, B1)                                                            \
    asm volatile("mma.sync.aligned.m16n8k16.row.col.f32.bf16.bf16.f32 "          \
                 "{%0,%1,%2,%3}, {%4,%5,%6,%7}, {%8,%9}, {%0,%1,%2,%3};"         \
                 : "+f"(acc[j][0]), "+f"(acc[j][1]), "+f"(acc[j][2]), "+f"(acc[j][3]) \
                 : "r"(A[0]), "r"(A[1]), "r"(A[2]), "r"(A[3]), "r"(B0), "r"(B1))
                MMA(ah, bh[a2 * 2], bh[a2 * 2 + 1]);
                MMA(ah, bl[a2 * 2], bl[a2 * 2 + 1]);
                MMA(al, bh[a2 * 2], bh[a2 * 2 + 1]);
#undef MMA
            }
        }
    }

    // ---- epilogue: D lane layout: rows lane>>2 (+8), cols (lane&3)*2 per atom ----
    int r1 = row0 + wid * 16 + (lane >> 2);
    int r2 = r1 + 8;
    int cb = (lane & 3) * 2;
    float is1 = 0.f, is2 = 0.f;
    if (r1 < N) is1 = rsqrtf((float)g_degi[r1]);
    if (r2 < N) is2 = rsqrtf((float)g_degi[r2]);
    float*  gp1 = g_g   + (size_t)r1 * HH;
    float*  gp2 = g_g   + (size_t)r2 * HH;
    __half* hp1 = g_g16 + (size_t)r1 * HH;
    __half* hp2 = g_g16 + (size_t)r2 * HH;

#pragma unroll
    for (int j = 0; j < 8; j++) {
        int c = j * 8 + cb;
        float b0 = b[c], b1 = b[c + 1];
        if (r1 < N) {
            float v0 = (acc[j][0] + b0) * is1;
            float v1 = (acc[j][1] + b1) * is1;
            *(float2*)(gp1 + c) = make_float2(v0, v1);
            __half2 h = __floats2half2_rn(v0, v1);
            *(__half2*)(hp1 + c) = h;
        }
        if (r2 < N) {
            float v0 = (acc[j][2] + b0) * is2;
            float v1 = (acc[j][3] + b1) * is2;
            *(float2*)(gp2 + c) = make_float2(v0, v1);
            __half2 h = __floats2half2_rn(v0, v1);
            *(__half2*)(hp2 + c) = h;
        }
    }
}

// ---------------- gather + finalize (fused) — R11 form, 16 lanes/node, MLP=8 --------
__global__ void k_gather(float* __restrict__ out,
                         const float* __restrict__ gamma,
                         const float* __restrict__ beta,
                         const float* __restrict__ mean,
                         const float* __restrict__ var,
                         int N) {
    int t = blockIdx.x * blockDim.x + threadIdx.x;
    int v = t >> 4, q = t & 15;
    if (v >= N) return;

    int beg = g_off[v];
    int dgi = g_degi[v];
    int end = beg + dgi;

    float4 acc = make_float4(0.f, 0.f, 0.f, 0.f);
    int i = beg;
    for (; i + 8 <= end; i += 8) {
        int idx[8];
#pragma unroll
        for (int e = 0; e < 8; e++) idx[e] = __ldg(&g_adj[i + e]);
        uint2 u[8];
#pragma unroll
        for (int e = 0; e < 8; e++)
            u[e] = __ldg((const uint2*)(g_g16 + (size_t)idx[e] * HH) + q);
#pragma unroll
        for (int e = 0; e < 8; e++) {
            float2 a  = __half22float2(*(const __half2*)&u[e].x);
            float2 bq = __half22float2(*(const __half2*)&u[e].y);
            acc.x += a.x; acc.y += a.y; acc.z += bq.x; acc.w += bq.y;
        }
    }
    for (; i < end; i++) {
        int d = __ldg(&g_adj[i]);
        uint2 u = __ldg((const uint2*)(g_g16 + (size_t)d * HH) + q);
        float2 a  = __half22float2(*(const __half2*)&u.x);
        float2 bq = __half22float2(*(const __half2*)&u.y);
        acc.x += a.x; acc.y += a.y; acc.z += bq.x; acc.w += bq.y;
    }

    float dg = (float)dgi;
    float hs = 0.5f * rsqrtf(dg);          // 0.5 * deg^-1/2
    float sc = 0.5f * dg * sqrtf(dg);      // 0.5 * deg^1.5
    float4 gs = __ldg((const float4*)(g_g + (size_t)v * HH) + q);

    int j = q << 2;
    float sv[4] = {acc.x, acc.y, acc.z, acc.w};
    float gv[4] = {gs.x, gs.y, gs.z, gs.w};
    float o[4];
#pragma unroll
    for (int c = 0; c < 4; c++) {
        float a = hs * sv[c] + sc * gv[c];
        float scale = gamma[j + c] * rsqrtf(var[j + c] + BN_EPS);
        o[c] = (a - mean[j + c]) * scale + beta[j + c];
    }
    ((float4*)out)[t] = make_float4(o[0], o[1], o[2], o[3]);
}

// ---------------- launch --------------------------------------------------------------
extern "C" void kernel_launch(void* const* d_in, const int* in_sizes, int n_in,
                              void* d_out, int out_size) {
    const float* X     = (const float*)d_in[0];
    const float* W     = (const float*)d_in[1];
    const float* b     = (const float*)d_in[2];
    const float* gamma = (const float*)d_in[3];
    const float* beta  = (const float*)d_in[4];
    const float* mean  = (const float*)d_in[5];
    const float* var   = (const float*)d_in[6];
    const int2*  edge  = (const int2*)d_in[7];

    int N = in_sizes[0] / FF;
    int E = in_sizes[7] / 2;
    float* out = (float*)d_out;

    static cudaStream_t s2 = nullptr;
    static cudaEvent_t evA = nullptr, evB = nullptr;
    static bool inited = false;
    if (!inited) {
        cudaStreamCreateWithFlags(&s2, cudaStreamNonBlocking);
        cudaEventCreateWithFlags(&evA, cudaEventDisableTiming);
        cudaEventCreateWithFlags(&evB, cudaEventDisableTiming);
        cudaFuncSetAttribute(k_gemm, cudaFuncAttributeMaxDynamicSharedMemorySize, SM_TOT);
        inited = true;
    }

    // main stream: zero -> deg -> (fork) -> gemm -> (join) -> gather
    k_zero<<<(N + 255) / 256, 256>>>(N);
    k_deg<<<(E + 255) / 256, 256>>>(edge, E);
    cudaEventRecord(evA, 0);

    // side stream: offal -> scatter (independent of gemm)
    cudaStreamWaitEvent(s2, evA, 0);
    k_offal<<<(N + 255) / 256, 256, 0, s2>>>(N);
    {
        int nt = (E + 1) / 2;
        k_scatter<<<(nt + 255) / 256, 256, 0, s2>>>((const int4*)edge, E);
    }
    cudaEventRecord(evB, s2);

    k_gemm<<<(N + 127) / 128, 256, SM_TOT>>>(X, W, b, N);
    cudaStreamWaitEvent(0, evB, 0);
    k_gather<<<(N * 16 + 255) / 256, 256>>>(out, gamma, beta, mean, var, N);
}